// round 5
// baseline (speedup 1.0000x reference)
#include <cuda_runtime.h>
#include <stdint.h>

#define D 8
#define DD 64
#define MAX_N 1024

// 1 bit per (src,dst) cell: is there an edge?
__device__ unsigned g_bitmap[MAX_N * MAX_N / 32];   // 128 KB

__global__ void clear_bitmap(int nwords) {
    int i = blockIdx.x * blockDim.x + threadIdx.x;
    if (i < nwords) g_bitmap[i] = 0u;
}

__global__ void set_bitmap(const int* __restrict__ ei, int e, int n) {
    int idx = blockIdx.x * blockDim.x + threadIdx.x;
    if (idx >= e) return;
    int cell = ei[idx] * n + ei[e + idx];
    atomicOr(&g_bitmap[cell >> 5], 1u << (cell & 31));
}

// Single pass over the full 256 MB output: write zeros everywhere, except
// cells flagged in the bitmap, where R = W @ |x_i - x_j| is computed inline.
// Duplicate edges produce identical values, so value is a pure function of
// (i, j) — no ordering needed.
__global__ void fill_kernel(const float* __restrict__ x,
                            const float* __restrict__ W,
                            float4* __restrict__ out,
                            int n, size_t n4) {
    size_t i = (size_t)blockIdx.x * blockDim.x + threadIdx.x;
    size_t stride = (size_t)gridDim.x * blockDim.x;
    for (; i < n4; i += stride) {
        unsigned cell = (unsigned)(i >> 4);           // 16 float4 per cell
        unsigned word = g_bitmap[cell >> 5];          // warp-broadcast load
        float4 v = make_float4(0.f, 0.f, 0.f, 0.f);
        if ((word >> (cell & 31)) & 1u) {
            unsigned src = cell / (unsigned)n;
            unsigned dst = cell % (unsigned)n;
            float dvec[D];
            #pragma unroll
            for (int m = 0; m < D; m++)
                dvec[m] = fabsf(__ldg(&x[src * D + m]) - __ldg(&x[dst * D + m]));
            int r = (int)(i & 15) * 4;                // first of 4 output rows
            float acc[4] = {0.f, 0.f, 0.f, 0.f};
            #pragma unroll
            for (int c = 0; c < 4; c++)
                #pragma unroll
                for (int m = 0; m < D; m++)
                    acc[c] += __ldg(&W[(r + c) * D + m]) * dvec[m];
            v = make_float4(acc[0], acc[1], acc[2], acc[3]);
        }
        out[i] = v;
    }
}

extern "C" void kernel_launch(void* const* d_in, const int* in_sizes, int n_in,
                              void* d_out, int out_size) {
    const float* x  = (const float*)d_in[0];
    const int*   ei = (const int*)d_in[1];    // int64 in reference, int32 here
    const float* W  = (const float*)d_in[2];
    float* out = (float*)d_out;

    int n = in_sizes[0] / D;     // 1024
    int e = in_sizes[1] / 2;     // 32768

    int nwords = (n * n) / 32;
    clear_bitmap<<<(nwords + 255) / 256, 256>>>(nwords);
    set_bitmap<<<(e + 255) / 256, 256>>>(ei, e, n);

    size_t n4 = (size_t)out_size / 4;   // out_size = n*n*64 floats
    fill_kernel<<<8192, 256>>>(x, W, (float4*)out, n, n4);
}

// round 6
// speedup vs baseline: 1.4058x; 1.4058x over previous
#include <cuda_runtime.h>
#include <stdint.h>

#define D 8
#define DD 64

// Grid-stride float4 zero fill: pure HBM-write-bound (measured ~6.7 TB/s).
__global__ void zero_kernel(float4* __restrict__ out, size_t n4) {
    size_t i = (size_t)blockIdx.x * blockDim.x + threadIdx.x;
    size_t stride = (size_t)gridDim.x * blockDim.x;
    const float4 z = make_float4(0.f, 0.f, 0.f, 0.f);
    for (; i < n4; i += stride) out[i] = z;
}

// 16 edges per 256-thread block, 16 threads per edge, 4 output rows per
// thread, one STG.128 each. No smem, no barriers: ei/x loads are
// warp-broadcast, W is L1-resident. Duplicate (src,dst) edges write
// identical values, so races are benign and deterministic.
__global__ void scatter_kernel(const float* __restrict__ x,
                               const int* __restrict__ ei,
                               const float* __restrict__ W,
                               float4* __restrict__ out4,
                               int e, int n) {
    int t = threadIdx.x;
    int edge = blockIdx.x * 16 + (t >> 4);
    if (edge >= e) return;
    int q = t & 15;                       // rows 4q .. 4q+3

    int src = __ldg(&ei[edge]);
    int dst = __ldg(&ei[e + edge]);

    const float4* xs = (const float4*)(x + src * D);
    const float4* xd = (const float4*)(x + dst * D);
    float4 a0 = __ldg(xs), a1 = __ldg(xs + 1);
    float4 b0 = __ldg(xd), b1 = __ldg(xd + 1);

    float dv[D];
    dv[0] = fabsf(a0.x - b0.x); dv[1] = fabsf(a0.y - b0.y);
    dv[2] = fabsf(a0.z - b0.z); dv[3] = fabsf(a0.w - b0.w);
    dv[4] = fabsf(a1.x - b1.x); dv[5] = fabsf(a1.y - b1.y);
    dv[6] = fabsf(a1.z - b1.z); dv[7] = fabsf(a1.w - b1.w);

    float acc[4];
    #pragma unroll
    for (int c = 0; c < 4; c++) {
        const float4* w = (const float4*)(W + (q * 4 + c) * D);
        float4 w0 = __ldg(w), w1 = __ldg(w + 1);
        acc[c] = w0.x * dv[0] + w0.y * dv[1] + w0.z * dv[2] + w0.w * dv[3]
               + w1.x * dv[4] + w1.y * dv[5] + w1.z * dv[6] + w1.w * dv[7];
    }

    size_t cell = (size_t)src * n + dst;
    out4[cell * 16 + q] = make_float4(acc[0], acc[1], acc[2], acc[3]);
}

extern "C" void kernel_launch(void* const* d_in, const int* in_sizes, int n_in,
                              void* d_out, int out_size) {
    const float* x  = (const float*)d_in[0];
    const int*   ei = (const int*)d_in[1];    // int64 in reference, int32 here
    const float* W  = (const float*)d_in[2];

    int n = in_sizes[0] / D;     // 1024
    int e = in_sizes[1] / 2;     // 32768

    size_t n4 = (size_t)out_size / 4;   // out_size = n*n*64 floats
    zero_kernel<<<4096, 256>>>((float4*)d_out, n4);

    scatter_kernel<<<(e + 15) / 16, 256>>>(x, ei, W, (float4*)d_out, e, n);
}

// round 7
// speedup vs baseline: 1.6256x; 1.1564x over previous
#include <cuda_runtime.h>
#include <stdint.h>

#define D 8
#define DD 64

// Grid-stride float4 zero fill: pure HBM-write-bound (measured ~6.7 TB/s).
__global__ void zero_kernel(float4* __restrict__ out, size_t n4) {
    size_t i = (size_t)blockIdx.x * blockDim.x + threadIdx.x;
    size_t stride = (size_t)gridDim.x * blockDim.x;
    const float4 z = make_float4(0.f, 0.f, 0.f, 0.f);
    for (; i < n4; i += stride) out[i] = z;
}

// Each thread owns 4 fixed output rows (q = t&15 -> rows 4q..4q+3) and keeps
// those 32 W coefficients in registers for the entire kernel. Groups of 16
// threads grid-stride over edges: per edge only broadcast ei/x loads, 32 FMAs,
// and one STG.128. Duplicate (src,dst) edges write identical values, so races
// are benign and deterministic.
__global__ void scatter_kernel(const float* __restrict__ x,
                               const int* __restrict__ ei,
                               const float* __restrict__ W,
                               float4* __restrict__ out4,
                               int e, int n) {
    int t = threadIdx.x;
    int q = t & 15;                          // rows 4q .. 4q+3

    // W rows for this thread, loaded once.
    float4 w[8];
    #pragma unroll
    for (int c = 0; c < 4; c++) {
        const float4* wp = (const float4*)(W + (q * 4 + c) * D);
        w[2 * c]     = __ldg(wp);
        w[2 * c + 1] = __ldg(wp + 1);
    }

    int group   = blockIdx.x * 16 + (t >> 4);
    int ngroups = gridDim.x * 16;

    #pragma unroll 2
    for (int edge = group; edge < e; edge += ngroups) {
        int src = __ldg(&ei[edge]);
        int dst = __ldg(&ei[e + edge]);

        const float4* xs = (const float4*)(x + src * D);
        const float4* xd = (const float4*)(x + dst * D);
        float4 a0 = __ldg(xs), a1 = __ldg(xs + 1);
        float4 b0 = __ldg(xd), b1 = __ldg(xd + 1);

        float dv[D];
        dv[0] = fabsf(a0.x - b0.x); dv[1] = fabsf(a0.y - b0.y);
        dv[2] = fabsf(a0.z - b0.z); dv[3] = fabsf(a0.w - b0.w);
        dv[4] = fabsf(a1.x - b1.x); dv[5] = fabsf(a1.y - b1.y);
        dv[6] = fabsf(a1.z - b1.z); dv[7] = fabsf(a1.w - b1.w);

        float acc[4];
        #pragma unroll
        for (int c = 0; c < 4; c++) {
            acc[c] = w[2*c].x   * dv[0] + w[2*c].y   * dv[1]
                   + w[2*c].z   * dv[2] + w[2*c].w   * dv[3]
                   + w[2*c+1].x * dv[4] + w[2*c+1].y * dv[5]
                   + w[2*c+1].z * dv[6] + w[2*c+1].w * dv[7];
        }

        size_t cell = (size_t)src * n + dst;
        out4[cell * 16 + q] = make_float4(acc[0], acc[1], acc[2], acc[3]);
    }
}

extern "C" void kernel_launch(void* const* d_in, const int* in_sizes, int n_in,
                              void* d_out, int out_size) {
    const float* x  = (const float*)d_in[0];
    const int*   ei = (const int*)d_in[1];    // int64 in reference, int32 here
    const float* W  = (const float*)d_in[2];

    int n = in_sizes[0] / D;     // 1024
    int e = in_sizes[1] / 2;     // 32768

    size_t n4 = (size_t)out_size / 4;   // out_size = n*n*64 floats
    zero_kernel<<<4096, 256>>>((float4*)d_out, n4);

    // 512 blocks * 16 groups = 8192 groups, 4 edges per group.
    scatter_kernel<<<512, 256>>>(x, ei, W, (float4*)d_out, e, n);
}